// round 1
// baseline (speedup 1.0000x reference)
#include <cuda_runtime.h>
#include <cstdint>

// Problem constants (fixed by the dataset)
#define IN_F    512
#define GATES   255
#define GATES_P 256
#define LEAVES  256
#define OUT_F   256
#define BM      64     // rows per block
#define KC      32     // K-chunk for gate GEMM
#define LC      32     // L-chunk for leaf GEMM
#define NTHREADS 256

// Scratch: z transposed to [leaf][out] for coalesced phase-3 tile loads.
__device__ float g_zT[LEAVES * OUT_F];

typedef unsigned long long u64;

__device__ __forceinline__ u64 pack_dup(float a) {
    u64 r; asm("mov.b64 %0, {%1, %1};" : "=l"(r) : "f"(a)); return r;
}
__device__ __forceinline__ u64 pack2(float lo, float hi) {
    u64 r; asm("mov.b64 %0, {%1, %2};" : "=l"(r) : "f"(lo), "f"(hi)); return r;
}
__device__ __forceinline__ u64 fma2(u64 a, u64 b, u64 c) {
    u64 d; asm("fma.rn.f32x2 %0, %1, %2, %3;" : "=l"(d) : "l"(a), "l"(b), "l"(c)); return d;
}
__device__ __forceinline__ float2 unpk(u64 v) {
    float2 f; asm("mov.b64 {%0, %1}, %2;" : "=f"(f.x), "=f"(f.y) : "l"(v)); return f;
}

__global__ void transpose_z_kernel(const float* __restrict__ z) {
    int idx = blockIdx.x * blockDim.x + threadIdx.x;   // 65536 threads
    int o = idx >> 8;
    int l = idx & 255;
    g_zT[l * OUT_F + o] = z[o * LEAVES + l];
}

// Dynamic smem layout (floats):
//   [0, 2048)          xs  [64][32]        (phase 1)         -- overlaps gl
//   [2048, 10240)      ws  [32][256]       (phase 1)         -- overlaps gl
//   [0, 16384)         gl  [64][256]       gates, then leaf  (phases 2,3)
//   [16384, 24576)     zs  [32][256]       (phase 3)
//   [24576, 24832)     gbs [256]
// total: 24832 floats = 99328 bytes
#define SMEM_FLOATS 24832

extern "C" __global__ void __launch_bounds__(NTHREADS, 2)
softtree_fused_kernel(const float* __restrict__ x,
                      const float* __restrict__ gw,
                      const float* __restrict__ gb,
                      float* __restrict__ out)
{
    extern __shared__ float smem[];
    float* xs  = smem;                  // [64][32]
    float* ws  = smem + BM * KC;        // [32][256]
    float* gl  = smem;                  // [64][256] gates then leaf
    float* zs  = smem + 16384;          // [32][256]
    float* gbs = smem + 16384 + 8192;   // [256]

    const int tid = threadIdx.x;
    const int tx  = tid & 31;           // 32 col-groups of 8 cols
    const int ty  = tid >> 5;           // 8 row-groups of 8 rows
    const int rbase = blockIdx.x * BM;

    gbs[tid] = (tid < GATES) ? gb[tid] : 0.0f;

    // 8x8 fp32 microtile, packed as 8 x 4 f32x2 accumulators
    u64 acc[8][4];
    #pragma unroll
    for (int i = 0; i < 8; i++)
        #pragma unroll
        for (int j = 0; j < 4; j++) acc[i][j] = 0ull;

    // ---------------- Phase 1: gate logits = x @ gw ----------------
    for (int kt = 0; kt < IN_F / KC; kt++) {
        __syncthreads();
        // load x tile [64][32] (2 float4 per thread, coalesced)
        #pragma unroll
        for (int t = 0; t < 2; t++) {
            int f  = tid + t * NTHREADS;     // float4 slot 0..511
            int r  = f >> 3;
            int kq = f & 7;
            float4 v = *(const float4*)&x[(size_t)(rbase + r) * IN_F + kt * KC + kq * 4];
            *(float4*)&xs[r * KC + kq * 4] = v;
        }
        // load gw tile [32][256] (gw is [512][255] row-major; pad col 255 with 0)
        #pragma unroll 8
        for (int t = 0; t < 32; t++) {
            int idx = tid + t * NTHREADS;
            int k = idx >> 8;
            int g = idx & 255;
            ws[k * GATES_P + g] = (g < GATES) ? gw[(size_t)(kt * KC + k) * GATES + g] : 0.0f;
        }
        __syncthreads();
        #pragma unroll 8
        for (int kk = 0; kk < KC; kk++) {
            const ulonglong2* bp = (const ulonglong2*)&ws[kk * GATES_P + tx * 8];
            ulonglong2 b01 = bp[0];
            ulonglong2 b23 = bp[1];
            u64 b0 = b01.x, b1 = b01.y, b2 = b23.x, b3 = b23.y;
            #pragma unroll
            for (int i = 0; i < 8; i++) {
                u64 a2 = pack_dup(xs[(ty * 8 + i) * KC + kk]);
                acc[i][0] = fma2(a2, b0, acc[i][0]);
                acc[i][1] = fma2(a2, b1, acc[i][1]);
                acc[i][2] = fma2(a2, b2, acc[i][2]);
                acc[i][3] = fma2(a2, b3, acc[i][3]);
            }
        }
    }
    __syncthreads();   // everyone done reading xs/ws before gl overwrites them

    // ---------------- Phase 2a: sigmoid -> gates in smem ----------------
    #pragma unroll
    for (int i = 0; i < 8; i++) {
        int r = ty * 8 + i;
        #pragma unroll
        for (int j = 0; j < 4; j++) {
            float2 v = unpk(acc[i][j]);
            int c = tx * 8 + j * 2;
            float l0 = v.x + gbs[c];
            float l1 = v.y + gbs[c + 1];
            gl[r * GATES_P + c]     = 1.0f / (1.0f + __expf(-l0));
            gl[r * GATES_P + c + 1] = 1.0f / (1.0f + __expf(-l1));
        }
    }
    __syncthreads();

    // ---------------- Phase 2b: tree products -> leaf probs ----------------
    // leaf l (0..255): depth d uses node (2^d - 1) + (l >> (8-d)),
    // factor = bit ? (1-g) : g with bit = (l >> (7-d)) & 1.
    // Depths 0..4 depend only on tx (shared across the thread's 8 leaves).
    #pragma unroll
    for (int i = 0; i < 8; i++) {
        const float* grow = &gl[(ty * 8 + i) * GATES_P];
        float common = 1.0f;
        #pragma unroll
        for (int d = 0; d < 5; d++) {
            int prefix = tx >> (5 - d);
            float g = grow[(1 << d) - 1 + prefix];
            int bit = (tx >> (4 - d)) & 1;
            common *= bit ? (1.0f - g) : g;
        }
        #pragma unroll
        for (int jp = 0; jp < 4; jp++) {
            float pv[2];
            #pragma unroll
            for (int s = 0; s < 2; s++) {
                int l = tx * 8 + jp * 2 + s;
                float p = common;
                #pragma unroll
                for (int d = 5; d < 8; d++) {
                    int prefix = l >> (8 - d);
                    float g = grow[(1 << d) - 1 + prefix];
                    int bit = (l >> (7 - d)) & 1;
                    p *= bit ? (1.0f - g) : g;
                }
                pv[s] = p;
            }
            acc[i][jp] = pack2(pv[0], pv[1]);   // reuse accumulators as staging
        }
    }
    __syncthreads();   // all reads of gates done before overwrite with leaf
    #pragma unroll
    for (int i = 0; i < 8; i++) {
        int r = ty * 8 + i;
        ulonglong2 s0, s1;
        s0.x = acc[i][0]; s0.y = acc[i][1];
        s1.x = acc[i][2]; s1.y = acc[i][3];
        *(ulonglong2*)&gl[r * GATES_P + tx * 8]     = s0;
        *(ulonglong2*)&gl[r * GATES_P + tx * 8 + 4] = s1;
    }

    // ---------------- Phase 3: out = leaf @ z^T ----------------
    #pragma unroll
    for (int i = 0; i < 8; i++)
        #pragma unroll
        for (int j = 0; j < 4; j++) acc[i][j] = 0ull;

    for (int lt = 0; lt < LEAVES / LC; lt++) {
        __syncthreads();
        // load zT tile [32][256] (coalesced read, conflict-free store)
        #pragma unroll 8
        for (int t = 0; t < 32; t++) {
            int idx = tid + t * NTHREADS;
            int lw = idx >> 8;
            int o  = idx & 255;
            zs[lw * OUT_F + o] = g_zT[(size_t)(lt * LC + lw) * OUT_F + o];
        }
        __syncthreads();
        #pragma unroll 8
        for (int lw = 0; lw < LC; lw++) {
            const ulonglong2* bp = (const ulonglong2*)&zs[lw * OUT_F + tx * 8];
            ulonglong2 b01 = bp[0];
            ulonglong2 b23 = bp[1];
            u64 b0 = b01.x, b1 = b01.y, b2 = b23.x, b3 = b23.y;
            #pragma unroll
            for (int i = 0; i < 8; i++) {
                u64 a2 = pack_dup(gl[(ty * 8 + i) * GATES_P + lt * LC + lw]);
                acc[i][0] = fma2(a2, b0, acc[i][0]);
                acc[i][1] = fma2(a2, b1, acc[i][1]);
                acc[i][2] = fma2(a2, b2, acc[i][2]);
                acc[i][3] = fma2(a2, b3, acc[i][3]);
            }
        }
    }

    // write output tile
    #pragma unroll
    for (int i = 0; i < 8; i++) {
        int r = rbase + ty * 8 + i;
        ulonglong2 s0, s1;
        s0.x = acc[i][0]; s0.y = acc[i][1];
        s1.x = acc[i][2]; s1.y = acc[i][3];
        *(ulonglong2*)&out[(size_t)r * OUT_F + tx * 8]     = s0;
        *(ulonglong2*)&out[(size_t)r * OUT_F + tx * 8 + 4] = s1;
    }
}

extern "C" void kernel_launch(void* const* d_in, const int* in_sizes, int n_in,
                              void* d_out, int out_size)
{
    const float* x  = (const float*)d_in[0];   // [B, 512]
    const float* gw = (const float*)d_in[1];   // [512, 255]
    const float* gb = (const float*)d_in[2];   // [255]
    const float* z  = (const float*)d_in[3];   // [256, 256]
    float* out = (float*)d_out;                // [B, 256]

    const int B = in_sizes[0] / IN_F;

    // transpose z -> g_zT (tiny, runs every call: deterministic & idempotent)
    transpose_z_kernel<<<(LEAVES * OUT_F) / 256, 256>>>(z);

    const int smem_bytes = SMEM_FLOATS * sizeof(float);
    cudaFuncSetAttribute(softtree_fused_kernel,
                         cudaFuncAttributeMaxDynamicSharedMemorySize, smem_bytes);
    softtree_fused_kernel<<<B / BM, NTHREADS, smem_bytes>>>(x, gw, gb, out);
}

// round 2
// speedup vs baseline: 1.0015x; 1.0015x over previous
#include <cuda_runtime.h>
#include <cstdint>

// Problem constants (fixed by the dataset)
#define IN_F    512
#define GATES   255
#define GATES_P 256
#define LEAVES  256
#define OUT_F   256
#define BM      64     // rows per block
#define KC      32     // K-chunk for gate GEMM
#define LC      32     // L-chunk for leaf GEMM
#define NTHREADS 256

// Scratch: z transposed to [leaf][out] for coalesced phase-3 tile loads.
__device__ float g_zT[LEAVES * OUT_F];

typedef unsigned long long u64;

__device__ __forceinline__ u64 pack_dup(float a) {
    u64 r; asm("mov.b64 %0, {%1, %1};" : "=l"(r) : "f"(a)); return r;
}
__device__ __forceinline__ u64 pack2(float lo, float hi) {
    u64 r; asm("mov.b64 %0, {%1, %2};" : "=l"(r) : "f"(lo), "f"(hi)); return r;
}
__device__ __forceinline__ u64 fma2(u64 a, u64 b, u64 c) {
    u64 d; asm("fma.rn.f32x2 %0, %1, %2, %3;" : "=l"(d) : "l"(a), "l"(b), "l"(c)); return d;
}
__device__ __forceinline__ float2 unpk(u64 v) {
    float2 f; asm("mov.b64 {%0, %1}, %2;" : "=f"(f.x), "=f"(f.y) : "l"(v)); return f;
}

__global__ void transpose_z_kernel(const float* __restrict__ z) {
    int idx = blockIdx.x * blockDim.x + threadIdx.x;   // 65536 threads
    int o = idx >> 8;
    int l = idx & 255;
    g_zT[l * OUT_F + o] = z[o * LEAVES + l];
}

// Dynamic smem layout (floats):
//   [0, 2048)          xs  [64][32]        (phase 1)         -- overlaps gl
//   [2048, 10240)      ws  [32][256]       (phase 1)         -- overlaps gl
//   [0, 16384)         gl  [64][256]       gates, then leaf  (phases 2,3)
//   [16384, 24576)     zs  [32][256]       (phase 3)
//   [24576, 24832)     gbs [256]
// total: 24832 floats = 99328 bytes
#define SMEM_FLOATS 24832

extern "C" __global__ void __launch_bounds__(NTHREADS, 2)
softtree_fused_kernel(const float* __restrict__ x,
                      const float* __restrict__ gw,
                      const float* __restrict__ gb,
                      float* __restrict__ out)
{
    extern __shared__ float smem[];
    float* xs  = smem;                  // [64][32]
    float* ws  = smem + BM * KC;        // [32][256]
    float* gl  = smem;                  // [64][256] gates then leaf
    float* zs  = smem + 16384;          // [32][256]
    float* gbs = smem + 16384 + 8192;   // [256]

    const int tid = threadIdx.x;
    const int tx  = tid & 31;           // 32 col-groups of 8 cols
    const int ty  = tid >> 5;           // 8 row-groups of 8 rows
    const int rbase = blockIdx.x * BM;

    gbs[tid] = (tid < GATES) ? gb[tid] : 0.0f;

    // 8x8 fp32 microtile, packed as 8 x 4 f32x2 accumulators
    u64 acc[8][4];
    #pragma unroll
    for (int i = 0; i < 8; i++)
        #pragma unroll
        for (int j = 0; j < 4; j++) acc[i][j] = 0ull;

    // ---------------- Phase 1: gate logits = x @ gw ----------------
    for (int kt = 0; kt < IN_F / KC; kt++) {
        __syncthreads();
        // load x tile [64][32] (2 float4 per thread, coalesced)
        #pragma unroll
        for (int t = 0; t < 2; t++) {
            int f  = tid + t * NTHREADS;     // float4 slot 0..511
            int r  = f >> 3;
            int kq = f & 7;
            float4 v = *(const float4*)&x[(size_t)(rbase + r) * IN_F + kt * KC + kq * 4];
            *(float4*)&xs[r * KC + kq * 4] = v;
        }
        // load gw tile [32][256] (gw is [512][255] row-major; pad col 255 with 0)
        #pragma unroll 8
        for (int t = 0; t < 32; t++) {
            int idx = tid + t * NTHREADS;
            int k = idx >> 8;
            int g = idx & 255;
            ws[k * GATES_P + g] = (g < GATES) ? gw[(size_t)(kt * KC + k) * GATES + g] : 0.0f;
        }
        __syncthreads();
        #pragma unroll 8
        for (int kk = 0; kk < KC; kk++) {
            const ulonglong2* bp = (const ulonglong2*)&ws[kk * GATES_P + tx * 8];
            ulonglong2 b01 = bp[0];
            ulonglong2 b23 = bp[1];
            u64 b0 = b01.x, b1 = b01.y, b2 = b23.x, b3 = b23.y;
            #pragma unroll
            for (int i = 0; i < 8; i++) {
                u64 a2 = pack_dup(xs[(ty * 8 + i) * KC + kk]);
                acc[i][0] = fma2(a2, b0, acc[i][0]);
                acc[i][1] = fma2(a2, b1, acc[i][1]);
                acc[i][2] = fma2(a2, b2, acc[i][2]);
                acc[i][3] = fma2(a2, b3, acc[i][3]);
            }
        }
    }
    __syncthreads();   // everyone done reading xs/ws before gl overwrites them

    // ---------------- Phase 2a: sigmoid -> gates in smem ----------------
    #pragma unroll
    for (int i = 0; i < 8; i++) {
        int r = ty * 8 + i;
        #pragma unroll
        for (int j = 0; j < 4; j++) {
            float2 v = unpk(acc[i][j]);
            int c = tx * 8 + j * 2;
            float l0 = v.x + gbs[c];
            float l1 = v.y + gbs[c + 1];
            gl[r * GATES_P + c]     = 1.0f / (1.0f + __expf(-l0));
            gl[r * GATES_P + c + 1] = 1.0f / (1.0f + __expf(-l1));
        }
    }
    __syncthreads();

    // ---------------- Phase 2b: tree products -> leaf probs ----------------
    // leaf l (0..255): depth d uses node (2^d - 1) + (l >> (8-d)),
    // factor = bit ? (1-g) : g with bit = (l >> (7-d)) & 1.
    // Depths 0..4 depend only on tx (shared across the thread's 8 leaves).
    #pragma unroll
    for (int i = 0; i < 8; i++) {
        const float* grow = &gl[(ty * 8 + i) * GATES_P];
        float common = 1.0f;
        #pragma unroll
        for (int d = 0; d < 5; d++) {
            int prefix = tx >> (5 - d);
            float g = grow[(1 << d) - 1 + prefix];
            int bit = (tx >> (4 - d)) & 1;
            common *= bit ? (1.0f - g) : g;
        }
        #pragma unroll
        for (int jp = 0; jp < 4; jp++) {
            float pv[2];
            #pragma unroll
            for (int s = 0; s < 2; s++) {
                int l = tx * 8 + jp * 2 + s;
                float p = common;
                #pragma unroll
                for (int d = 5; d < 8; d++) {
                    int prefix = l >> (8 - d);
                    float g = grow[(1 << d) - 1 + prefix];
                    int bit = (l >> (7 - d)) & 1;
                    p *= bit ? (1.0f - g) : g;
                }
                pv[s] = p;
            }
            acc[i][jp] = pack2(pv[0], pv[1]);   // reuse accumulators as staging
        }
    }
    __syncthreads();   // all reads of gates done before overwrite with leaf
    #pragma unroll
    for (int i = 0; i < 8; i++) {
        int r = ty * 8 + i;
        ulonglong2 s0, s1;
        s0.x = acc[i][0]; s0.y = acc[i][1];
        s1.x = acc[i][2]; s1.y = acc[i][3];
        *(ulonglong2*)&gl[r * GATES_P + tx * 8]     = s0;
        *(ulonglong2*)&gl[r * GATES_P + tx * 8 + 4] = s1;
    }

    // ---------------- Phase 3: out = leaf @ z^T ----------------
    #pragma unroll
    for (int i = 0; i < 8; i++)
        #pragma unroll
        for (int j = 0; j < 4; j++) acc[i][j] = 0ull;

    for (int lt = 0; lt < LEAVES / LC; lt++) {
        __syncthreads();
        // load zT tile [32][256] (coalesced read, conflict-free store)
        #pragma unroll 8
        for (int t = 0; t < 32; t++) {
            int idx = tid + t * NTHREADS;
            int lw = idx >> 8;
            int o  = idx & 255;
            zs[lw * OUT_F + o] = g_zT[(size_t)(lt * LC + lw) * OUT_F + o];
        }
        __syncthreads();
        #pragma unroll 8
        for (int lw = 0; lw < LC; lw++) {
            const ulonglong2* bp = (const ulonglong2*)&zs[lw * OUT_F + tx * 8];
            ulonglong2 b01 = bp[0];
            ulonglong2 b23 = bp[1];
            u64 b0 = b01.x, b1 = b01.y, b2 = b23.x, b3 = b23.y;
            #pragma unroll
            for (int i = 0; i < 8; i++) {
                u64 a2 = pack_dup(gl[(ty * 8 + i) * GATES_P + lt * LC + lw]);
                acc[i][0] = fma2(a2, b0, acc[i][0]);
                acc[i][1] = fma2(a2, b1, acc[i][1]);
                acc[i][2] = fma2(a2, b2, acc[i][2]);
                acc[i][3] = fma2(a2, b3, acc[i][3]);
            }
        }
    }

    // write output tile
    #pragma unroll
    for (int i = 0; i < 8; i++) {
        int r = rbase + ty * 8 + i;
        ulonglong2 s0, s1;
        s0.x = acc[i][0]; s0.y = acc[i][1];
        s1.x = acc[i][2]; s1.y = acc[i][3];
        *(ulonglong2*)&out[(size_t)r * OUT_F + tx * 8]     = s0;
        *(ulonglong2*)&out[(size_t)r * OUT_F + tx * 8 + 4] = s1;
    }
}

extern "C" void kernel_launch(void* const* d_in, const int* in_sizes, int n_in,
                              void* d_out, int out_size)
{
    const float* x  = (const float*)d_in[0];   // [B, 512]
    const float* gw = (const float*)d_in[1];   // [512, 255]
    const float* gb = (const float*)d_in[2];   // [255]
    const float* z  = (const float*)d_in[3];   // [256, 256]
    float* out = (float*)d_out;                // [B, 256]

    const int B = in_sizes[0] / IN_F;

    // transpose z -> g_zT (tiny, runs every call: deterministic & idempotent)
    transpose_z_kernel<<<(LEAVES * OUT_F) / 256, 256>>>(z);

    const int smem_bytes = SMEM_FLOATS * sizeof(float);
    cudaFuncSetAttribute(softtree_fused_kernel,
                         cudaFuncAttributeMaxDynamicSharedMemorySize, smem_bytes);
    softtree_fused_kernel<<<B / BM, NTHREADS, smem_bytes>>>(x, gw, gb, out);
}